// round 6
// baseline (speedup 1.0000x reference)
#include <cuda_runtime.h>

#define DD 128
#define NODES_PER_TILE 64
#define E_MAX 800000
#define R_MAX 512
#define SPLIT 8
#define SCHUNK 4096

// ---- scratch (device globals; no allocation allowed) ----
__device__ int  g_off[R_MAX + 1];     // per-type offsets (exclusive scan)
__device__ int  g_cursor[R_MAX];      // per-type reservation cursors
__device__ int4 g_edges[E_MAX];       // sorted {src, dst, scale_bits, pad}

#define REDV4(ptr, v)                                                   \
    asm volatile("red.global.add.v4.f32 [%0], {%1,%2,%3,%4};"           \
                 :: "l"(ptr), "f"((v).x), "f"((v).y), "f"((v).z), "f"((v).w) \
                 : "memory")

// ---------------------------------------------------------------------------
// Fused layer kernel. Block role by interleaved blockIdx:
//   i % F == F-1  -> dense block (i/F):  red-add (h@loop_w + dec*(prev@time_w))
//   else          -> edge slot j = (i/F)*(F-1) + i%F: type = j%R, split = j/R
// Output must be pre-zeroed; all contributions are commutative red.adds.
// ---------------------------------------------------------------------------
__global__ __launch_bounds__(256, 2)
void fused_layer_kernel(const float* __restrict__ h,
                        const float* __restrict__ prev,
                        const float* __restrict__ time_diff,
                        const float* __restrict__ loop_w,
                        const float* __restrict__ time_w,
                        const float* __restrict__ W,
                        float* __restrict__ out,
                        int N, int R, int F)
{
    const int i = blockIdx.x;

    if ((i % F) == (F - 1)) {
        // ================= dense role =================
        __shared__ float w1s[16][DD];
        __shared__ float w2s[16][DD];
        __shared__ float hs[16][NODES_PER_TILE];
        __shared__ float ps[16][NODES_PER_TILE];

        const int tid  = threadIdx.x;
        const int colg = tid & 15;
        const int nrow = tid >> 4;
        const int tile = (i / F) * NODES_PER_TILE;

        float4 a1[4][2];
        float4 a2[4][2];
#pragma unroll
        for (int s = 0; s < 4; s++)
#pragma unroll
            for (int j = 0; j < 2; j++) {
                a1[s][j] = make_float4(0.f, 0.f, 0.f, 0.f);
                a2[s][j] = make_float4(0.f, 0.f, 0.f, 0.f);
            }

        const int stage_n  = tid >> 2;
        const int stage_c4 = tid & 3;
        const int stage_node = tile + stage_n;
        const bool stage_ok = (stage_node < N);

#pragma unroll 1
        for (int kc = 0; kc < 8; kc++) {
            const int k0 = kc * 16;
            __syncthreads();
#pragma unroll
            for (int r = 0; r < 2; r++) {
                int idx = tid + r * 256;
                int kk  = idx >> 5;
                int c4  = idx & 31;
                float4 v1 = ((const float4*)(loop_w + (size_t)(k0 + kk) * DD))[c4];
                float4 v2 = ((const float4*)(time_w + (size_t)(k0 + kk) * DD))[c4];
                ((float4*)&w1s[kk][0])[c4] = v1;
                ((float4*)&w2s[kk][0])[c4] = v2;
            }
            {
                float4 vh = make_float4(0.f, 0.f, 0.f, 0.f);
                float4 vp = make_float4(0.f, 0.f, 0.f, 0.f);
                if (stage_ok) {
                    vh = ((const float4*)(h    + (size_t)stage_node * DD + k0))[stage_c4];
                    vp = ((const float4*)(prev + (size_t)stage_node * DD + k0))[stage_c4];
                }
                int kk = stage_c4 * 4;
                hs[kk + 0][stage_n] = vh.x; hs[kk + 1][stage_n] = vh.y;
                hs[kk + 2][stage_n] = vh.z; hs[kk + 3][stage_n] = vh.w;
                ps[kk + 0][stage_n] = vp.x; ps[kk + 1][stage_n] = vp.y;
                ps[kk + 2][stage_n] = vp.z; ps[kk + 3][stage_n] = vp.w;
            }
            __syncthreads();

#pragma unroll
            for (int kk = 0; kk < 16; kk++) {
                float4 wa = ((const float4*)&w1s[kk][0])[colg * 2 + 0];
                float4 wb = ((const float4*)&w1s[kk][0])[colg * 2 + 1];
                float4 ua = ((const float4*)&w2s[kk][0])[colg * 2 + 0];
                float4 ub = ((const float4*)&w2s[kk][0])[colg * 2 + 1];
#pragma unroll
                for (int s = 0; s < 4; s++) {
                    float hv = hs[kk][nrow + s * 16];
                    float pv = ps[kk][nrow + s * 16];
                    a1[s][0].x += hv * wa.x; a1[s][0].y += hv * wa.y;
                    a1[s][0].z += hv * wa.z; a1[s][0].w += hv * wa.w;
                    a1[s][1].x += hv * wb.x; a1[s][1].y += hv * wb.y;
                    a1[s][1].z += hv * wb.z; a1[s][1].w += hv * wb.w;
                    a2[s][0].x += pv * ua.x; a2[s][0].y += pv * ua.y;
                    a2[s][0].z += pv * ua.z; a2[s][0].w += pv * ua.w;
                    a2[s][1].x += pv * ub.x; a2[s][1].y += pv * ub.y;
                    a2[s][1].z += pv * ub.z; a2[s][1].w += pv * ub.w;
                }
            }
        }

#pragma unroll
        for (int s = 0; s < 4; s++) {
            int node = tile + nrow + s * 16;
            if (node >= N) continue;
            float dec = __expf(-__ldg(time_diff + node) * 0.1f);
            float4 o0, o1;
            o0.x = a1[s][0].x + dec * a2[s][0].x;
            o0.y = a1[s][0].y + dec * a2[s][0].y;
            o0.z = a1[s][0].z + dec * a2[s][0].z;
            o0.w = a1[s][0].w + dec * a2[s][0].w;
            o1.x = a1[s][1].x + dec * a2[s][1].x;
            o1.y = a1[s][1].y + dec * a2[s][1].y;
            o1.z = a1[s][1].z + dec * a2[s][1].z;
            o1.w = a1[s][1].w + dec * a2[s][1].w;
            float* op = out + (size_t)node * DD + colg * 8;
            REDV4(op + 0, o0);
            REDV4(op + 4, o1);
        }
    } else {
        // ================= edge role =================
        const int j = (i / F) * (F - 1) + (i % F);
        const int t = j % R;
        const int bsplit = j / R;
        if (bsplit >= SPLIT) return;

        const int lane = threadIdx.x & 31;
        const int warp = threadIdx.x >> 5;

        const int start = g_off[t];
        const int end   = g_off[t + 1];
        if (start >= end) return;

        const float4* wp = (const float4*)(W + (size_t)t * 512) + lane * 4;
        const float4 w0 = __ldg(wp + 0);
        const float4 w1 = __ldg(wp + 1);
        const float4 w2 = __ldg(wp + 2);
        const float4 w3 = __ldg(wp + 3);

        const int stride = 8 * SPLIT;
        int e = start + bsplit * 8 + warp;

        for (; e + stride < end; e += 2 * stride) {
            const int4 mdA = __ldg(g_edges + e);
            const int4 mdB = __ldg(g_edges + e + stride);

            float4 hA = __ldg((const float4*)(h + (size_t)mdA.x * DD) + lane);
            float4 hB = __ldg((const float4*)(h + (size_t)mdB.x * DD) + lane);

            const float scA = __int_as_float(mdA.z);
            const float scB = __int_as_float(mdB.z);

            float4 mA, mB;
            mA.x = hA.x * w0.x + hA.y * w1.x + hA.z * w2.x + hA.w * w3.x;
            mA.y = hA.x * w0.y + hA.y * w1.y + hA.z * w2.y + hA.w * w3.y;
            mA.z = hA.x * w0.z + hA.y * w1.z + hA.z * w2.z + hA.w * w3.z;
            mA.w = hA.x * w0.w + hA.y * w1.w + hA.z * w2.w + hA.w * w3.w;
            mB.x = hB.x * w0.x + hB.y * w1.x + hB.z * w2.x + hB.w * w3.x;
            mB.y = hB.x * w0.y + hB.y * w1.y + hB.z * w2.y + hB.w * w3.y;
            mB.z = hB.x * w0.z + hB.y * w1.z + hB.z * w2.z + hB.w * w3.z;
            mB.w = hB.x * w0.w + hB.y * w1.w + hB.z * w2.w + hB.w * w3.w;
            mA.x *= scA; mA.y *= scA; mA.z *= scA; mA.w *= scA;
            mB.x *= scB; mB.y *= scB; mB.z *= scB; mB.w *= scB;

            REDV4(out + (size_t)mdA.y * DD + lane * 4, mA);
            REDV4(out + (size_t)mdB.y * DD + lane * 4, mB);
        }

        if (e < end) {
            const int4 md = __ldg(g_edges + e);
            float4 hv = __ldg((const float4*)(h + (size_t)md.x * DD) + lane);
            const float sc = __int_as_float(md.z);

            float4 m;
            m.x = hv.x * w0.x + hv.y * w1.x + hv.z * w2.x + hv.w * w3.x;
            m.y = hv.x * w0.y + hv.y * w1.y + hv.z * w2.y + hv.w * w3.y;
            m.z = hv.x * w0.z + hv.y * w1.z + hv.z * w2.z + hv.w * w3.z;
            m.w = hv.x * w0.w + hv.y * w1.w + hv.z * w2.w + hv.w * w3.w;
            m.x *= sc; m.y *= sc; m.z *= sc; m.w *= sc;

            REDV4(out + (size_t)md.y * DD + lane * 4, m);
        }
    }
}

// ---------------------------------------------------------------------------
// Sort pipeline (counting sort by relation type) + zero + relu utilities.
// ---------------------------------------------------------------------------
__global__ void zero_out_kernel(float4* __restrict__ p, int n4)
{
    int i = blockIdx.x * blockDim.x + threadIdx.x;
    if (i < n4) p[i] = make_float4(0.f, 0.f, 0.f, 0.f);
}

__global__ void zero_kernel(int R)
{
    int i = blockIdx.x * blockDim.x + threadIdx.x;
    if (i <= R) g_off[i] = 0;
    if (i < R)  g_cursor[i] = 0;
}

__global__ __launch_bounds__(256)
void hist_kernel(const int* __restrict__ etyp, int E, int R)
{
    __shared__ int lh[R_MAX];
    for (int i = threadIdx.x; i < R; i += blockDim.x) lh[i] = 0;
    __syncthreads();
    for (int e = blockIdx.x * blockDim.x + threadIdx.x; e < E;
         e += gridDim.x * blockDim.x)
        atomicAdd(&lh[__ldg(etyp + e)], 1);
    __syncthreads();
    for (int i = threadIdx.x; i < R; i += blockDim.x) {
        int v = lh[i];
        if (v) atomicAdd(&g_off[i + 1], v);
    }
}

__global__ void scan_kernel(int R)
{
    if (threadIdx.x == 0) {
        int acc = 0;
        for (int i = 1; i <= R; i++) { acc += g_off[i]; g_off[i] = acc; }
    }
}

__global__ __launch_bounds__(256)
void scatter_kernel(const int* __restrict__ esrc,
                    const int* __restrict__ edst,
                    const int* __restrict__ etyp,
                    const float* __restrict__ enorm,
                    const float* __restrict__ nnorm,
                    int E, int R)
{
    __shared__ int lbase[R_MAX];
    __shared__ int lcur[R_MAX];

    const int e0 = blockIdx.x * SCHUNK;
    const int e1 = min(e0 + SCHUNK, E);

    for (int i = threadIdx.x; i < R; i += blockDim.x) {
        lbase[i] = 0;
        lcur[i]  = 0;
    }
    __syncthreads();

    for (int e = e0 + threadIdx.x; e < e1; e += blockDim.x)
        atomicAdd(&lbase[__ldg(etyp + e)], 1);
    __syncthreads();

    for (int i = threadIdx.x; i < R; i += blockDim.x) {
        int cnt = lbase[i];
        lbase[i] = cnt ? (g_off[i] + atomicAdd(&g_cursor[i], cnt)) : 0;
    }
    __syncthreads();

    for (int e = e0 + threadIdx.x; e < e1; e += blockDim.x) {
        int t = __ldg(etyp + e);
        int d = __ldg(edst + e);
        int pos = lbase[t] + atomicAdd(&lcur[t], 1);
        float sc = __ldg(enorm + e) * __ldg(nnorm + d);
        g_edges[pos] = make_int4(__ldg(esrc + e), d, __float_as_int(sc), 0);
    }
}

__global__ void relu_kernel(float* __restrict__ x, int n)
{
    int i = blockIdx.x * blockDim.x + threadIdx.x;
    if (i < n) {
        float v = x[i];
        x[i] = v > 0.f ? v : 0.f;
    }
}

extern "C" void kernel_launch(void* const* d_in, const int* in_sizes, int n_in,
                              void* d_out, int out_size)
{
    const float* h   = (const float*)d_in[0];
    const float* fp  = (const float*)d_in[1];
    const float* sp  = (const float*)d_in[2];
    const float* td  = (const float*)d_in[3];
    const int*   es  = (const int*)  d_in[4];
    const int*   ed  = (const int*)  d_in[5];
    const int*   et  = (const int*)  d_in[6];
    const float* en  = (const float*)d_in[7];
    const float* nn  = (const float*)d_in[8];
    const float* W1  = (const float*)d_in[9];
    const float* W2  = (const float*)d_in[10];
    const float* lw1 = (const float*)d_in[11];
    const float* lw2 = (const float*)d_in[12];
    const float* tw1 = (const float*)d_in[13];
    const float* tw2 = (const float*)d_in[14];

    const int N = in_sizes[3];            // time_diff is (N,1)
    const int E = in_sizes[4];            // edge_src is (E,)
    const int R = in_sizes[9] / 512;      // W1 is (R, 512)

    float* h1 = (float*)d_out;
    float* h2 = h1 + (size_t)N * DD;

    const int D_BLOCKS = (N + NODES_PER_TILE - 1) / NODES_PER_TILE;
    const int E_BLOCKS = R * SPLIT;
    // interleave factor: one dense block every F blocks
    const int F = 1 + (E_BLOCKS + D_BLOCKS - 1) / D_BLOCKS;
    const int T_BLOCKS = D_BLOCKS * F;

    const int scatterBlocks = (E + SCHUNK - 1) / SCHUNK;
    const int n4 = N * DD / 4;            // float4 count per buffer

    // ---- prep: zero both outputs, sort edges by relation type ----
    zero_out_kernel<<<(2 * n4 + 255) / 256, 256>>>((float4*)d_out, 2 * n4);
    zero_kernel    <<<(R + 256) / 256, 256>>>(R);
    hist_kernel    <<<256, 256>>>(et, E, R);
    scan_kernel    <<<1, 32>>>(R);
    scatter_kernel <<<scatterBlocks, 256>>>(es, ed, et, en, nn, E, R);

    // ---- layer 1 (dense + edge concurrent, all writes are red.add) ----
    fused_layer_kernel<<<T_BLOCKS, 256>>>(h, fp, td, lw1, tw1, W1, h1, N, R, F);

    // ---- layer 2 ----
    fused_layer_kernel<<<T_BLOCKS, 256>>>(h1, sp, td, lw2, tw2, W2, h2, N, R, F);
    relu_kernel<<<((size_t)N * DD + 255) / 256, 256>>>(h2, N * DD);
}

// round 7
// speedup vs baseline: 1.3181x; 1.3181x over previous
#include <cuda_runtime.h>

#define DD 128
#define E_MAX 800000
#define R_MAX 512
#define SPLIT 8
#define SCHUNK 4096

// ---- scratch (device globals; no allocation allowed) ----
__device__ int   g_off[R_MAX + 1];
__device__ int   g_cursor[R_MAX];
__device__ int4  g_edges[E_MAX];           // sorted {src, dst, scale_bits, pad}
__device__ float g_Whi[2 * 256 * 128];     // stacked [loop_w; time_w], tf32 hi
__device__ float g_Wlo[2 * 256 * 128];     // tf32 lo

#define REDV4(ptr, v)                                                   \
    asm volatile("red.global.add.v4.f32 [%0], {%1,%2,%3,%4};"           \
                 :: "l"(ptr), "f"((v).x), "f"((v).y), "f"((v).z), "f"((v).w) \
                 : "memory")

#define MMA_TF32(c, a, b)                                               \
    asm volatile("mma.sync.aligned.m16n8k8.row.col.f32.tf32.tf32.f32 "  \
                 "{%0,%1,%2,%3}, {%4,%5,%6,%7}, {%8,%9}, {%0,%1,%2,%3};" \
                 : "+f"((c)[0]), "+f"((c)[1]), "+f"((c)[2]), "+f"((c)[3]) \
                 : "r"((a)[0]), "r"((a)[1]), "r"((a)[2]), "r"((a)[3]),  \
                   "r"((b)[0]), "r"((b)[1]))

__device__ __forceinline__ unsigned f2tf32(float v)
{
    unsigned r;
    asm("cvt.rna.tf32.f32 %0, %1;" : "=r"(r) : "f"(v));
    return r;
}

// ---------------------------------------------------------------------------
// Weight split: W' = [loop_w; time_w] (256x128) -> tf32 hi/lo, both layers.
// ---------------------------------------------------------------------------
__global__ void split_w_kernel(const float* __restrict__ lw1,
                               const float* __restrict__ tw1,
                               const float* __restrict__ lw2,
                               const float* __restrict__ tw2)
{
    int idx = blockIdx.x * blockDim.x + threadIdx.x;
    if (idx >= 2 * 256 * 128) return;
    int layer = idx >> 15;
    int k = (idx >> 7) & 255;
    int n = idx & 127;
    const float* lw = layer ? lw2 : lw1;
    const float* tw = layer ? tw2 : tw1;
    float v = (k < 128) ? lw[k * 128 + n] : tw[(k - 128) * 128 + n];
    unsigned hb = f2tf32(v);
    float lo = v - __uint_as_float(hb);
    g_Whi[idx] = __uint_as_float(hb);
    g_Wlo[idx] = __uint_as_float(f2tf32(lo));
}

// ---------------------------------------------------------------------------
// Tensor-core dense kernel (3xTF32):
//   out[n,:] = [h[n,:], dec(n)*prev[n,:]] @ W'  (K=256)
// Block: 256 threads, tile M=128 x N=128. Warp grid 4x2, each warp m32 x n64.
// smem (dynamic): AsHi[128][36], AsLo[128][36], WsHi[32][132], WsLo[32][132].
// ---------------------------------------------------------------------------
#define AS_STRIDE 36
#define WS_STRIDE 132
#define OFF_ASHI 0
#define OFF_ASLO (128 * AS_STRIDE)
#define OFF_WSHI (2 * 128 * AS_STRIDE)
#define OFF_WSLO (2 * 128 * AS_STRIDE + 32 * WS_STRIDE)
#define DENSE_SMEM_FLOATS (2 * 128 * AS_STRIDE + 2 * 32 * WS_STRIDE)

__global__ __launch_bounds__(256, 1)
void dense_tc_kernel(const float* __restrict__ h,
                     const float* __restrict__ prev,
                     const float* __restrict__ time_diff,
                     float* __restrict__ out, int N, int layer)
{
    extern __shared__ float sm[];
    float* AsHi = sm + OFF_ASHI;
    float* AsLo = sm + OFF_ASLO;
    float* WsHi = sm + OFF_WSHI;
    float* WsLo = sm + OFF_WSLO;

    const float* whi = g_Whi + layer * 32768;
    const float* wlo = g_Wlo + layer * 32768;

    const int tid  = threadIdx.x;
    const int wid  = tid >> 5;
    const int lane = tid & 31;
    const int g = lane >> 2;          // 0..7
    const int t = lane & 3;           // 0..3
    const int mbase = (wid & 3) * 32; // warp m offset
    const int nbase = (wid >> 2) * 64;// warp n offset
    const int tileBase = blockIdx.x * 128;

    // staging assignment: thread -> row r, 16 cols starting at c0
    const int sr  = tid >> 1;
    const int sc0 = (tid & 1) * 16;
    const int snode = tileBase + sr;
    const bool sok = (snode < N);
    const float dec = sok ? __expf(-__ldg(time_diff + snode) * 0.1f) : 0.f;

    // W staging assignment: thread -> row kk, 16 cols at wc0
    const int skk  = tid >> 3;          // 0..31
    const int swc0 = (tid & 7) * 16;    // 0..112

    float acc[2][8][4];
#pragma unroll
    for (int mi = 0; mi < 2; mi++)
#pragma unroll
        for (int nt = 0; nt < 8; nt++)
#pragma unroll
            for (int c = 0; c < 4; c++) acc[mi][nt][c] = 0.f;

#pragma unroll 1
    for (int kc = 0; kc < 8; kc++) {
        __syncthreads();
        // ---- stage A (convert fp32 -> tf32 hi/lo) ----
        {
            float vals[16];
            if (sok) {
                const float* src = (kc < 4)
                    ? (h    + (size_t)snode * DD + kc * 32 + sc0)
                    : (prev + (size_t)snode * DD + (kc - 4) * 32 + sc0);
#pragma unroll
                for (int j = 0; j < 4; j++) {
                    float4 v = __ldg((const float4*)src + j);
                    vals[j * 4 + 0] = v.x; vals[j * 4 + 1] = v.y;
                    vals[j * 4 + 2] = v.z; vals[j * 4 + 3] = v.w;
                }
                if (kc >= 4) {
#pragma unroll
                    for (int j = 0; j < 16; j++) vals[j] *= dec;
                }
            } else {
#pragma unroll
                for (int j = 0; j < 16; j++) vals[j] = 0.f;
            }
            float his[16], los[16];
#pragma unroll
            for (int j = 0; j < 16; j++) {
                unsigned hb = f2tf32(vals[j]);
                his[j] = __uint_as_float(hb);
                los[j] = __uint_as_float(f2tf32(vals[j] - his[j]));
            }
            float* dhi = AsHi + sr * AS_STRIDE + sc0;
            float* dlo = AsLo + sr * AS_STRIDE + sc0;
#pragma unroll
            for (int j = 0; j < 4; j++) {
                ((float4*)dhi)[j] = make_float4(his[j*4], his[j*4+1], his[j*4+2], his[j*4+3]);
                ((float4*)dlo)[j] = make_float4(los[j*4], los[j*4+1], los[j*4+2], los[j*4+3]);
            }
        }
        // ---- stage W (already split; straight copy) ----
        {
            const float* shi = whi + (kc * 32 + skk) * 128 + swc0;
            const float* slo = wlo + (kc * 32 + skk) * 128 + swc0;
            float* dhi = WsHi + skk * WS_STRIDE + swc0;
            float* dlo = WsLo + skk * WS_STRIDE + swc0;
#pragma unroll
            for (int j = 0; j < 4; j++) {
                ((float4*)dhi)[j] = __ldg((const float4*)shi + j);
                ((float4*)dlo)[j] = __ldg((const float4*)slo + j);
            }
        }
        __syncthreads();

        // ---- compute: 4 k8 steps ----
#pragma unroll
        for (int ks = 0; ks < 4; ks++) {
            const int k0 = ks * 8;
            unsigned ahi[2][4], alo[2][4];
#pragma unroll
            for (int mi = 0; mi < 2; mi++) {
                int r0 = (mbase + mi * 16 + g) * AS_STRIDE + k0 + t;
                int r1 = r0 + 8 * AS_STRIDE;
                ahi[mi][0] = __float_as_uint(AsHi[r0]);
                ahi[mi][1] = __float_as_uint(AsHi[r1]);
                ahi[mi][2] = __float_as_uint(AsHi[r0 + 4]);
                ahi[mi][3] = __float_as_uint(AsHi[r1 + 4]);
                alo[mi][0] = __float_as_uint(AsLo[r0]);
                alo[mi][1] = __float_as_uint(AsLo[r1]);
                alo[mi][2] = __float_as_uint(AsLo[r0 + 4]);
                alo[mi][3] = __float_as_uint(AsLo[r1 + 4]);
            }
            unsigned bhi[8][2], blo[8][2];
#pragma unroll
            for (int nt = 0; nt < 8; nt++) {
                int col = nbase + nt * 8 + g;
                int i0 = (k0 + t) * WS_STRIDE + col;
                int i1 = i0 + 4 * WS_STRIDE;
                bhi[nt][0] = __float_as_uint(WsHi[i0]);
                bhi[nt][1] = __float_as_uint(WsHi[i1]);
                blo[nt][0] = __float_as_uint(WsLo[i0]);
                blo[nt][1] = __float_as_uint(WsLo[i1]);
            }
#pragma unroll
            for (int mi = 0; mi < 2; mi++)
#pragma unroll
                for (int nt = 0; nt < 8; nt++) {
                    MMA_TF32(acc[mi][nt], ahi[mi], bhi[nt]);
                    MMA_TF32(acc[mi][nt], ahi[mi], blo[nt]);
                    MMA_TF32(acc[mi][nt], alo[mi], bhi[nt]);
                }
        }
    }

    // ---- epilogue: plain STG (dense runs before edge REDs) ----
#pragma unroll
    for (int mi = 0; mi < 2; mi++) {
        int row0 = tileBase + mbase + mi * 16 + g;
        int row1 = row0 + 8;
#pragma unroll
        for (int nt = 0; nt < 8; nt++) {
            int col = nbase + nt * 8 + 2 * t;
            if (row0 < N)
                *(float2*)(out + (size_t)row0 * DD + col) =
                    make_float2(acc[mi][nt][0], acc[mi][nt][1]);
            if (row1 < N)
                *(float2*)(out + (size_t)row1 * DD + col) =
                    make_float2(acc[mi][nt][2], acc[mi][nt][3]);
        }
    }
}

// ---------------------------------------------------------------------------
// Sort pipeline: counting sort of edges by relation type.
// ---------------------------------------------------------------------------
__global__ void zero_kernel(int R)
{
    int i = blockIdx.x * blockDim.x + threadIdx.x;
    if (i <= R) g_off[i] = 0;
    if (i < R)  g_cursor[i] = 0;
}

__global__ __launch_bounds__(256)
void hist_kernel(const int* __restrict__ etyp, int E, int R)
{
    __shared__ int lh[R_MAX];
    for (int i = threadIdx.x; i < R; i += blockDim.x) lh[i] = 0;
    __syncthreads();
    for (int e = blockIdx.x * blockDim.x + threadIdx.x; e < E;
         e += gridDim.x * blockDim.x)
        atomicAdd(&lh[__ldg(etyp + e)], 1);
    __syncthreads();
    for (int i = threadIdx.x; i < R; i += blockDim.x) {
        int v = lh[i];
        if (v) atomicAdd(&g_off[i + 1], v);
    }
}

// parallel inclusive scan over g_off[0..R] (R+1 <= 512), one block.
__global__ __launch_bounds__(512)
void scan_kernel(int R)
{
    __shared__ int buf[512];
    const int tid = threadIdx.x;
    buf[tid] = (tid <= R) ? g_off[tid] : 0;
    __syncthreads();
#pragma unroll
    for (int d = 1; d < 512; d <<= 1) {
        int v = (tid >= d) ? buf[tid - d] : 0;
        __syncthreads();
        buf[tid] += v;
        __syncthreads();
    }
    if (tid <= R) g_off[tid] = buf[tid];
}

__global__ __launch_bounds__(256)
void scatter_kernel(const int* __restrict__ esrc,
                    const int* __restrict__ edst,
                    const int* __restrict__ etyp,
                    const float* __restrict__ enorm,
                    const float* __restrict__ nnorm,
                    int E, int R)
{
    __shared__ int lbase[R_MAX];
    __shared__ int lcur[R_MAX];

    const int e0 = blockIdx.x * SCHUNK;
    const int e1 = min(e0 + SCHUNK, E);

    for (int i = threadIdx.x; i < R; i += blockDim.x) {
        lbase[i] = 0;
        lcur[i]  = 0;
    }
    __syncthreads();

    for (int e = e0 + threadIdx.x; e < e1; e += blockDim.x)
        atomicAdd(&lbase[__ldg(etyp + e)], 1);
    __syncthreads();

    for (int i = threadIdx.x; i < R; i += blockDim.x) {
        int cnt = lbase[i];
        lbase[i] = cnt ? (g_off[i] + atomicAdd(&g_cursor[i], cnt)) : 0;
    }
    __syncthreads();

    for (int e = e0 + threadIdx.x; e < e1; e += blockDim.x) {
        int t = __ldg(etyp + e);
        int d = __ldg(edst + e);
        int pos = lbase[t] + atomicAdd(&lcur[t], 1);
        float sc = __ldg(enorm + e) * __ldg(nnorm + d);
        g_edges[pos] = make_int4(__ldg(esrc + e), d, __float_as_int(sc), 0);
    }
}

// ---------------------------------------------------------------------------
// Sorted edge kernel, 2-wide (R5, known good).
// ---------------------------------------------------------------------------
__global__ __launch_bounds__(256)
void edge_sorted_kernel(const float* __restrict__ h,
                        const float* __restrict__ W,
                        float* __restrict__ out)
{
    const int t    = blockIdx.x;
    const int lane = threadIdx.x & 31;
    const int warp = threadIdx.x >> 5;

    const int start = g_off[t];
    const int end   = g_off[t + 1];
    if (start >= end) return;

    const float4* wp = (const float4*)(W + (size_t)t * 512) + lane * 4;
    const float4 w0 = __ldg(wp + 0);
    const float4 w1 = __ldg(wp + 1);
    const float4 w2 = __ldg(wp + 2);
    const float4 w3 = __ldg(wp + 3);

    const int stride = 8 * SPLIT;
    int e = start + blockIdx.y * 8 + warp;

    for (; e + stride < end; e += 2 * stride) {
        const int4 mdA = __ldg(g_edges + e);
        const int4 mdB = __ldg(g_edges + e + stride);

        float4 hA = __ldg((const float4*)(h + (size_t)mdA.x * DD) + lane);
        float4 hB = __ldg((const float4*)(h + (size_t)mdB.x * DD) + lane);

        const float scA = __int_as_float(mdA.z);
        const float scB = __int_as_float(mdB.z);

        float4 mA, mB;
        mA.x = hA.x * w0.x + hA.y * w1.x + hA.z * w2.x + hA.w * w3.x;
        mA.y = hA.x * w0.y + hA.y * w1.y + hA.z * w2.y + hA.w * w3.y;
        mA.z = hA.x * w0.z + hA.y * w1.z + hA.z * w2.z + hA.w * w3.z;
        mA.w = hA.x * w0.w + hA.y * w1.w + hA.z * w2.w + hA.w * w3.w;
        mB.x = hB.x * w0.x + hB.y * w1.x + hB.z * w2.x + hB.w * w3.x;
        mB.y = hB.x * w0.y + hB.y * w1.y + hB.z * w2.y + hB.w * w3.y;
        mB.z = hB.x * w0.z + hB.y * w1.z + hB.z * w2.z + hB.w * w3.z;
        mB.w = hB.x * w0.w + hB.y * w1.w + hB.z * w2.w + hB.w * w3.w;
        mA.x *= scA; mA.y *= scA; mA.z *= scA; mA.w *= scA;
        mB.x *= scB; mB.y *= scB; mB.z *= scB; mB.w *= scB;

        REDV4(out + (size_t)mdA.y * DD + lane * 4, mA);
        REDV4(out + (size_t)mdB.y * DD + lane * 4, mB);
    }

    if (e < end) {
        const int4 md = __ldg(g_edges + e);
        float4 hv = __ldg((const float4*)(h + (size_t)md.x * DD) + lane);
        const float sc = __int_as_float(md.z);

        float4 m;
        m.x = hv.x * w0.x + hv.y * w1.x + hv.z * w2.x + hv.w * w3.x;
        m.y = hv.x * w0.y + hv.y * w1.y + hv.z * w2.y + hv.w * w3.y;
        m.z = hv.x * w0.z + hv.y * w1.z + hv.z * w2.z + hv.w * w3.z;
        m.w = hv.x * w0.w + hv.y * w1.w + hv.z * w2.w + hv.w * w3.w;
        m.x *= sc; m.y *= sc; m.z *= sc; m.w *= sc;

        REDV4(out + (size_t)md.y * DD + lane * 4, m);
    }
}

__global__ void relu_kernel(float* __restrict__ x, int n)
{
    int i = blockIdx.x * blockDim.x + threadIdx.x;
    if (i < n) {
        float v = x[i];
        x[i] = v > 0.f ? v : 0.f;
    }
}

extern "C" void kernel_launch(void* const* d_in, const int* in_sizes, int n_in,
                              void* d_out, int out_size)
{
    const float* h   = (const float*)d_in[0];
    const float* fp  = (const float*)d_in[1];
    const float* sp  = (const float*)d_in[2];
    const float* td  = (const float*)d_in[3];
    const int*   es  = (const int*)  d_in[4];
    const int*   ed  = (const int*)  d_in[5];
    const int*   et  = (const int*)  d_in[6];
    const float* en  = (const float*)d_in[7];
    const float* nn  = (const float*)d_in[8];
    const float* W1  = (const float*)d_in[9];
    const float* W2  = (const float*)d_in[10];
    const float* lw1 = (const float*)d_in[11];
    const float* lw2 = (const float*)d_in[12];
    const float* tw1 = (const float*)d_in[13];
    const float* tw2 = (const float*)d_in[14];

    const int N = in_sizes[3];            // time_diff is (N,1)
    const int E = in_sizes[4];            // edge_src is (E,)
    const int R = in_sizes[9] / 512;      // W1 is (R, 512)

    float* h1 = (float*)d_out;
    float* h2 = h1 + (size_t)N * DD;

    const int denseBlocks   = (N + 127) / 128;
    const int scatterBlocks = (E + SCHUNK - 1) / SCHUNK;
    const int denseSmem     = DENSE_SMEM_FLOATS * sizeof(float);
    dim3 edgeGrid(R, SPLIT);

    static int attrDone = 0;
    if (!attrDone) {
        cudaFuncSetAttribute(dense_tc_kernel,
                             cudaFuncAttributeMaxDynamicSharedMemorySize,
                             denseSmem);
        attrDone = 1;
    }

    // ---- prep: weight split + counting sort (reused by both layers) ----
    split_w_kernel<<<(2 * 256 * 128 + 255) / 256, 256>>>(lw1, tw1, lw2, tw2);
    zero_kernel   <<<(R + 256) / 256, 256>>>(R);
    hist_kernel   <<<256, 256>>>(et, E, R);
    scan_kernel   <<<1, 512>>>(R);
    scatter_kernel<<<scatterBlocks, 256>>>(es, ed, et, en, nn, E, R);

    // ---- layer 1 ----
    dense_tc_kernel<<<denseBlocks, 256, denseSmem>>>(h, fp, td, h1, N, 0);
    edge_sorted_kernel<<<edgeGrid, 256>>>(h, W1, h1);

    // ---- layer 2 ----
    dense_tc_kernel<<<denseBlocks, 256, denseSmem>>>(h1, sp, td, h2, N, 1);
    edge_sorted_kernel<<<edgeGrid, 256>>>(h1, W2, h2);
    relu_kernel<<<((size_t)N * DD + 255) / 256, 256>>>(h2, N * DD);
}